// round 15
// baseline (speedup 1.0000x reference)
#include <cuda_runtime.h>
#include <cuda_bf16.h>
#include <cstdint>

// ResidualStreamMapping: RMSNorm-scale + skinny GEMM (D=4096 -> 16) + Sinkhorn(20)
//
// Round 15: R14 mainloop exactly; prep_kernel FUSED into rsm. Each of the
// 32768 rsm threads packs one Bfrag element, then an in-grid release/acquire
// barrier (sound: all 256 blocks co-resident at 2 blocks/SM). x prefetch for
// chunks 0-1 issues BEFORE the barrier so prep+spin hide under the DRAM fill.
// Counter reset via cudaMemsetAsync node (replaces the prep kernel node).

#define D        4096
#define NJ       16
#define KCH      64                       // d per pipeline chunk
#define NCH      (D / KCH)                // 64
#define WARPS    4
#define THREADS  128
#define NBLOCKS  256                      // 1024 warp-tiles = 16384 rows / 16

#define PITCHB   288                      // x row pitch in bytes (72 f32) - conflict-free
#define XSTG     (16 * PITCHB)            // 4608 per warp-stage
#define BSTG     2048                     // 64k x 16n bf16 fragments per chunk
#define NSTAGE   3
#define XWARP    (NSTAGE * XSTG)          // 13824
#define BWARP    (NSTAGE * BSTG)          // 6144
#define OFF_B    (WARPS * XWARP)          // 55296
#define SMEM_B   (OFF_B + WARPS * BWARP)  // 79872  -> 2 blocks/SM (co-residency!)

typedef unsigned long long ull;

// B fragments: [kc16 0..255][lane 0..31][4 u32] (exact m16n8k16 B layout, alpha-folded)
__device__ __align__(16) uint32_t Bfrag[256 * 32 * 4];   // 128 KB
__device__ int bar_ctr;                                  // grid barrier counter

// ---------- helpers ----------
__device__ __forceinline__ void fma2(ull& c, ull a, ull b) {
    asm("fma.rn.f32x2 %0, %1, %2, %0;" : "+l"(c) : "l"(a), "l"(b));
}
__device__ __forceinline__ float2 unpk(ull v) {
    float2 f; asm("mov.b64 {%0, %1}, %2;" : "=f"(f.x), "=f"(f.y) : "l"(v)); return f;
}
__device__ __forceinline__ void cpa16h(unsigned dst, const void* src, ull pol) {
    asm volatile("cp.async.cg.shared.global.L2::cache_hint [%0], [%1], 16, %2;"
                 :: "r"(dst), "l"(src), "l"(pol));
}
__device__ __forceinline__ ull lds64(unsigned a) {
    ull r; asm volatile("ld.shared.b64 %0, [%1];" : "=l"(r) : "r"(a)); return r;
}
__device__ __forceinline__ uint32_t cvt2(ull x) {   // f32 pair (lo=k, hi=k+1) -> bf16x2
    float2 p = unpk(x);
    uint32_t r; asm("cvt.rn.bf16x2.f32 %0, %1, %2;" : "=r"(r) : "f"(p.y), "f"(p.x));
    return r;
}
__device__ __forceinline__ void mma16816(float* c, const uint32_t* a,
                                         uint32_t b0, uint32_t b1) {
    asm volatile("mma.sync.aligned.m16n8k16.row.col.f32.bf16.bf16.f32 "
                 "{%0,%1,%2,%3}, {%4,%5,%6,%7}, {%8,%9}, {%0,%1,%2,%3};"
                 : "+f"(c[0]), "+f"(c[1]), "+f"(c[2]), "+f"(c[3])
                 : "r"(a[0]), "r"(a[1]), "r"(a[2]), "r"(a[3]), "r"(b0), "r"(b1));
}

// ---------- main kernel (prep fused) ----------
__global__ void __launch_bounds__(THREADS, 2)
rsm_kernel(const float* __restrict__ x, const float* __restrict__ W,
           const float* __restrict__ bias, const float* __restrict__ alpha,
           float* __restrict__ out)
{
    extern __shared__ __align__(16) unsigned char sm[];
    const unsigned sb = (unsigned)__cvta_generic_to_shared(sm);

    const int tid  = threadIdx.x;
    const int lane = tid & 31;
    const int warp = tid >> 5;

    const long long row0 = ((long long)blockIdx.x * WARPS + warp) * 16;

    const unsigned xw = sb + (unsigned)(warp * XWARP);
    const unsigned bw = sb + (unsigned)(OFF_B + warp * BWARP);

    // L2 policies: x = evict_first (pure stream), B = evict_last (hot 128KB)
    ull pol_x, pol_b;
    asm("createpolicy.fractional.L2::evict_first.b64 %0, 1.0;" : "=l"(pol_x));
    asm("createpolicy.fractional.L2::evict_last.b64 %0, 1.0;"  : "=l"(pol_b));

    auto prefetch_x = [&](int c) {
        const unsigned xs = xw + (unsigned)((c % NSTAGE) * XSTG);
#pragma unroll
        for (int i = 0; i < 8; ++i) {
            int g = lane + i * 32;              // 256 granules: 16 rows x 16
            int row = g >> 4, q = g & 15;
            cpa16h(xs + (unsigned)(row * PITCHB + q * 16),
                   x + (row0 + row) * D + c * KCH + q * 4, pol_x);
        }
    };
    auto prefetch_b = [&](int c) {
        const unsigned bs = bw + (unsigned)((c % NSTAGE) * BSTG);
        const uint8_t* bsrc = (const uint8_t*)Bfrag + (size_t)c * BSTG;
#pragma unroll
        for (int i = 0; i < 4; ++i) {
            int g = lane + i * 32;
            cpa16h(bs + (unsigned)(g * 16), bsrc + g * 16, pol_b);
        }
    };

    // ---- fused prep: this thread packs ONE Bfrag element ----
    {
        const float a = *alpha;
        int t = blockIdx.x * THREADS + tid;   // 0..32767
        int kc   = t >> 7;                    // k16 chunk 0..255
        int rem  = t & 127;
        int bl   = rem >> 2;                  // fragment lane
        int r    = rem & 3;
        int tl   = r >> 1;                    // n-tile (0: n0-7, 1: n8-15)
        int half = r & 1;                     // k half (0: k0-7, 1: k8-15)
        int n = (bl >> 2) + 8 * tl;
        int k = kc * 16 + (bl & 3) * 2 + 8 * half;
        float w0 = a * __ldg(W + n * D + k);
        float w1 = a * __ldg(W + n * D + k + 1);
        uint32_t packed;
        asm("cvt.rn.bf16x2.f32 %0, %1, %2;" : "=r"(packed) : "f"(w1), "f"(w0));
        Bfrag[t] = packed;
    }

    // ---- start x DRAM traffic NOW (no Bfrag dependence) ----
    prefetch_x(0); prefetch_x(1);

    // ---- in-grid barrier: release stores, then acquire-spin ----
    __threadfence();
    __syncthreads();
    if (tid == 0) atomicAdd(&bar_ctr, 1);
    for (;;) {
        int v;
        asm volatile("ld.acquire.gpu.b32 %0, [%1];" : "=r"(v) : "l"(&bar_ctr));
        if (v >= NBLOCKS) break;
    }

    // Bfrag fully written chip-wide: issue B prefetches, form groups
    prefetch_b(0); asm volatile("cp.async.commit_group;");   // g0 = {x0,x1,b0}
    prefetch_b(1); asm volatile("cp.async.commit_group;");   // g1 = {b1}

    // fragment addressing: r0 = lane>>2, i = lane&3
    const unsigned fr0 = xw + (unsigned)((lane >> 2) * PITCHB + (lane & 3) * 8);
    const unsigned fr8 = fr0 + 8 * PITCHB;
    const unsigned bfr = bw + (unsigned)(lane * 16);

    float acc[8];                 // 2 n8-tiles x 4
#pragma unroll
    for (int i = 0; i < 8; ++i) acc[i] = 0.0f;
    ull ssqa = 0ull, ssqb = 0ull; // rows r0 and r0+8

#pragma unroll 1
    for (int c = 0; c < NCH; ++c) {
        if (c + 2 < NCH) { prefetch_x(c + 2); prefetch_b(c + 2); }
        asm volatile("cp.async.commit_group;");
        asm volatile("cp.async.wait_group 2;" ::: "memory");   // chunk c arrived

        const unsigned st = (unsigned)((c % NSTAGE) * XSTG);
        const unsigned bt = (unsigned)((c % NSTAGE) * BSTG);

#pragma unroll
        for (int s = 0; s < 4; ++s) {                          // 4 k16 sub-chunks
            ull x0 = lds64(fr0 + st + s * 64);                 // (r0,   k0-7 pair)
            ull x1 = lds64(fr8 + st + s * 64);                 // (r0+8, k0-7 pair)
            ull x2 = lds64(fr0 + st + s * 64 + 32);            // (r0,   k8-15)
            ull x3 = lds64(fr8 + st + s * 64 + 32);            // (r0+8, k8-15)

            fma2(ssqa, x0, x0); fma2(ssqb, x1, x1);
            fma2(ssqa, x2, x2); fma2(ssqb, x3, x3);

            uint32_t a[4] = { cvt2(x0), cvt2(x1), cvt2(x2), cvt2(x3) };

            uint4 bv;
            asm volatile("ld.shared.v4.b32 {%0, %1, %2, %3}, [%4];"
                         : "=r"(bv.x), "=r"(bv.y), "=r"(bv.z), "=r"(bv.w)
                         : "r"(bfr + bt + (unsigned)(s * 512)));

            mma16816(acc,     a, bv.x, bv.y);   // n 0-7
            mma16816(acc + 4, a, bv.z, bv.w);   // n 8-15
        }
    }

    asm volatile("cp.async.wait_group 0;" ::: "memory");       // drain before smem reuse

    // ---- ssq reduce across the 4 lanes sharing each row ----
    float2 pa = unpk(ssqa), pb = unpk(ssqb);
    float sa = pa.x + pa.y, sb2 = pb.x + pb.y;
    sa  += __shfl_xor_sync(0xffffffffu, sa, 1);
    sa  += __shfl_xor_sync(0xffffffffu, sa, 2);
    sb2 += __shfl_xor_sync(0xffffffffu, sb2, 1);
    sb2 += __shfl_xor_sync(0xffffffffu, sb2, 2);

    // ---- stash D + ssq into this warp's (now free) x-stage smem ----
    float* dsm = (float*)(sm + warp * XWARP);   // 16 rows x 16 cols
    float* ssm = dsm + 256;
    {
        const int q = lane >> 2, i = lane & 3;
        dsm[q * 16 + 2 * i]            = acc[0];
        dsm[q * 16 + 2 * i + 1]        = acc[1];
        dsm[(q + 8) * 16 + 2 * i]      = acc[2];
        dsm[(q + 8) * 16 + 2 * i + 1]  = acc[3];
        dsm[q * 16 + 8 + 2 * i]        = acc[4];
        dsm[q * 16 + 9 + 2 * i]        = acc[5];
        dsm[(q + 8) * 16 + 8 + 2 * i]  = acc[6];
        dsm[(q + 8) * 16 + 9 + 2 * i]  = acc[7];
        if (i == 0) { ssm[q] = sa; ssm[q + 8] = sb2; }
    }
    __syncwarp();

    // ---- lanes 0-15: one row each -> scale, exp, Sinkhorn(20), store ----
    if (lane < 16) {
        const int row = lane;
        const float scale = rsqrtf(ssm[row] * (1.0f / (float)D) + 1.1920929e-07f);

        float m[16];
#pragma unroll
        for (int j = 0; j < 16; ++j)
            m[j] = __expf(fmaf(scale, dsm[row * 16 + j], bias[j]));

#pragma unroll 4
        for (int it = 0; it < 20; ++it) {
#pragma unroll
            for (int j = 0; j < 4; ++j) {              // column normalize
                float cs = m[j] + m[4 + j] + m[8 + j] + m[12 + j];
                float rc = __fdividef(1.0f, cs + 1e-8f);
                m[j] *= rc; m[4 + j] *= rc; m[8 + j] *= rc; m[12 + j] *= rc;
            }
#pragma unroll
            for (int i = 0; i < 4; ++i) {              // row normalize
                float rs = m[4 * i] + m[4 * i + 1] + m[4 * i + 2] + m[4 * i + 3];
                float rc = __fdividef(1.0f, rs + 1e-8f);
                m[4 * i] *= rc; m[4 * i + 1] *= rc; m[4 * i + 2] *= rc; m[4 * i + 3] *= rc;
            }
        }

        float4* o = (float4*)(out + (row0 + row) * NJ);
        o[0] = make_float4(m[0],  m[1],  m[2],  m[3]);
        o[1] = make_float4(m[4],  m[5],  m[6],  m[7]);
        o[2] = make_float4(m[8],  m[9],  m[10], m[11]);
        o[3] = make_float4(m[12], m[13], m[14], m[15]);
    }
}

extern "C" void kernel_launch(void* const* d_in, const int* in_sizes, int n_in,
                              void* d_out, int out_size)
{
    const float* x     = (const float*)d_in[0];
    const float* W     = (const float*)d_in[1];
    const float* bias  = (const float*)d_in[2];
    const float* alpha = (const float*)d_in[3];
    float* out = (float*)d_out;

    // reset the grid-barrier counter (memset node: graph-capturable, no alloc)
    void* ctr_addr = nullptr;
    cudaGetSymbolAddress(&ctr_addr, bar_ctr);
    cudaMemsetAsync(ctr_addr, 0, sizeof(int), 0);

    cudaFuncSetAttribute(rsm_kernel, cudaFuncAttributeMaxDynamicSharedMemorySize, SMEM_B);

    rsm_kernel<<<NBLOCKS, THREADS, SMEM_B>>>(x, W, bias, alpha, out);
}

// round 16
// speedup vs baseline: 1.0648x; 1.0648x over previous
#include <cuda_runtime.h>
#include <cuda_bf16.h>
#include <cstdint>

// ResidualStreamMapping: RMSNorm-scale + skinny GEMM (D=4096 -> 16) + Sinkhorn(20)
//
// Round 16: R14 (best: 55.3us) with ONE change: B cp.async uses .ca (L1-enabled)
// so the ~8x per-SM re-fetch of each Bfrag chunk (4 warps x 2 blocks stage the
// same 2KB) hits L1 instead of L2. x stays .cg/evict_first (streaming).
// R15's fused grid barrier reverted (-3.8us regression from CTA launch skew).

#define D        4096
#define NJ       16
#define KCH      64                       // d per pipeline chunk
#define NCH      (D / KCH)                // 64
#define WARPS    4
#define THREADS  128
#define NBLOCKS  256                      // 1024 warp-tiles = 16384 rows / 16

#define PITCHB   288                      // x row pitch in bytes (72 f32) - conflict-free
#define XSTG     (16 * PITCHB)            // 4608 per warp-stage
#define BSTG     2048                     // 64k x 16n bf16 fragments per chunk
#define NSTAGE   3
#define XWARP    (NSTAGE * XSTG)          // 13824
#define BWARP    (NSTAGE * BSTG)          // 6144
#define OFF_B    (WARPS * XWARP)          // 55296
#define SMEM_B   (OFF_B + WARPS * BWARP)  // 79872  -> 2 blocks/SM

typedef unsigned long long ull;

// B fragments: [kc16 0..255][lane 0..31][4 u32] (exact m16n8k16 B layout, alpha-folded)
__device__ __align__(16) uint32_t Bfrag[256 * 32 * 4];   // 128 KB

// ---------- helpers ----------
__device__ __forceinline__ void fma2(ull& c, ull a, ull b) {
    asm("fma.rn.f32x2 %0, %1, %2, %0;" : "+l"(c) : "l"(a), "l"(b));
}
__device__ __forceinline__ float2 unpk(ull v) {
    float2 f; asm("mov.b64 {%0, %1}, %2;" : "=f"(f.x), "=f"(f.y) : "l"(v)); return f;
}
__device__ __forceinline__ void cpa16_cg(unsigned dst, const void* src, ull pol) {
    asm volatile("cp.async.cg.shared.global.L2::cache_hint [%0], [%1], 16, %2;"
                 :: "r"(dst), "l"(src), "l"(pol));
}
__device__ __forceinline__ void cpa16_ca(unsigned dst, const void* src, ull pol) {
    asm volatile("cp.async.ca.shared.global.L2::cache_hint [%0], [%1], 16, %2;"
                 :: "r"(dst), "l"(src), "l"(pol));
}
__device__ __forceinline__ ull lds64(unsigned a) {
    ull r; asm volatile("ld.shared.b64 %0, [%1];" : "=l"(r) : "r"(a)); return r;
}
__device__ __forceinline__ uint32_t cvt2(ull x) {   // f32 pair (lo=k, hi=k+1) -> bf16x2
    float2 p = unpk(x);
    uint32_t r; asm("cvt.rn.bf16x2.f32 %0, %1, %2;" : "=r"(r) : "f"(p.y), "f"(p.x));
    return r;
}
__device__ __forceinline__ void mma16816(float* c, const uint32_t* a,
                                         uint32_t b0, uint32_t b1) {
    asm volatile("mma.sync.aligned.m16n8k16.row.col.f32.bf16.bf16.f32 "
                 "{%0,%1,%2,%3}, {%4,%5,%6,%7}, {%8,%9}, {%0,%1,%2,%3};"
                 : "+f"(c[0]), "+f"(c[1]), "+f"(c[2]), "+f"(c[3])
                 : "r"(a[0]), "r"(a[1]), "r"(a[2]), "r"(a[3]), "r"(b0), "r"(b1));
}

// ---------- prep: pack alpha*W into per-lane m16n8k16 B fragments ----------
__global__ void prep_kernel(const float* __restrict__ W, const float* __restrict__ alpha) {
    const float a = *alpha;
    int t = blockIdx.x * blockDim.x + threadIdx.x;   // 0..32767
    int kc   = t >> 7;          // k16 chunk 0..255
    int rem  = t & 127;
    int lane = rem >> 2;
    int r    = rem & 3;
    int tl   = r >> 1;          // n-tile (0: n0-7, 1: n8-15)
    int half = r & 1;           // k half (0: k0-7, 1: k8-15)
    int n = (lane >> 2) + 8 * tl;
    int k = kc * 16 + (lane & 3) * 2 + 8 * half;
    float w0 = a * W[n * D + k];
    float w1 = a * W[n * D + k + 1];
    uint32_t packed;
    asm("cvt.rn.bf16x2.f32 %0, %1, %2;" : "=r"(packed) : "f"(w1), "f"(w0));
    Bfrag[t] = packed;          // byte offset = kc*512 + lane*16 + r*4
}

// ---------- main kernel ----------
__global__ void __launch_bounds__(THREADS, 2)
rsm_kernel(const float* __restrict__ x, const float* __restrict__ bias,
           float* __restrict__ out)
{
    extern __shared__ __align__(16) unsigned char sm[];
    const unsigned sb = (unsigned)__cvta_generic_to_shared(sm);

    const int tid  = threadIdx.x;
    const int lane = tid & 31;
    const int warp = tid >> 5;

    const long long row0 = ((long long)blockIdx.x * WARPS + warp) * 16;

    const unsigned xw = sb + (unsigned)(warp * XWARP);
    const unsigned bw = sb + (unsigned)(OFF_B + warp * BWARP);

    // L2 policies: x = evict_first (pure stream), B = evict_last (hot 128KB)
    ull pol_x, pol_b;
    asm("createpolicy.fractional.L2::evict_first.b64 %0, 1.0;" : "=l"(pol_x));
    asm("createpolicy.fractional.L2::evict_last.b64 %0, 1.0;"  : "=l"(pol_b));

    // per-warp chunk prefetch (x f32 tile .cg + B fragment tile .ca), self-paced
    auto prefetch = [&](int c) {
        const unsigned xs = xw + (unsigned)((c % NSTAGE) * XSTG);
#pragma unroll
        for (int i = 0; i < 8; ++i) {
            int g = lane + i * 32;              // 256 granules: 16 rows x 16
            int row = g >> 4, q = g & 15;
            cpa16_cg(xs + (unsigned)(row * PITCHB + q * 16),
                     x + (row0 + row) * D + c * KCH + q * 4, pol_x);
        }
        const unsigned bs = bw + (unsigned)((c % NSTAGE) * BSTG);
        const uint8_t* bsrc = (const uint8_t*)Bfrag + (size_t)c * BSTG;
#pragma unroll
        for (int i = 0; i < 4; ++i) {
            int g = lane + i * 32;
            cpa16_ca(bs + (unsigned)(g * 16), bsrc + g * 16, pol_b);
        }
    };

    prefetch(0); asm volatile("cp.async.commit_group;");
    prefetch(1); asm volatile("cp.async.commit_group;");

    // fragment addressing: r0 = lane>>2, i = lane&3
    const unsigned fr0 = xw + (unsigned)((lane >> 2) * PITCHB + (lane & 3) * 8);
    const unsigned fr8 = fr0 + 8 * PITCHB;
    const unsigned bfr = bw + (unsigned)(lane * 16);

    float acc[8];                 // 2 n8-tiles x 4
#pragma unroll
    for (int i = 0; i < 8; ++i) acc[i] = 0.0f;
    ull ssqa = 0ull, ssqb = 0ull; // rows r0 and r0+8

#pragma unroll 1
    for (int c = 0; c < NCH; ++c) {
        if (c + 2 < NCH) prefetch(c + 2);
        asm volatile("cp.async.commit_group;");
        asm volatile("cp.async.wait_group 2;" ::: "memory");   // chunk c arrived

        const unsigned st = (unsigned)((c % NSTAGE) * XSTG);
        const unsigned bt = (unsigned)((c % NSTAGE) * BSTG);

#pragma unroll
        for (int s = 0; s < 4; ++s) {                          // 4 k16 sub-chunks
            ull x0 = lds64(fr0 + st + s * 64);                 // (r0,   k0-7 pair)
            ull x1 = lds64(fr8 + st + s * 64);                 // (r0+8, k0-7 pair)
            ull x2 = lds64(fr0 + st + s * 64 + 32);            // (r0,   k8-15)
            ull x3 = lds64(fr8 + st + s * 64 + 32);            // (r0+8, k8-15)

            fma2(ssqa, x0, x0); fma2(ssqb, x1, x1);
            fma2(ssqa, x2, x2); fma2(ssqb, x3, x3);

            uint32_t a[4] = { cvt2(x0), cvt2(x1), cvt2(x2), cvt2(x3) };

            uint4 bv;
            asm volatile("ld.shared.v4.b32 {%0, %1, %2, %3}, [%4];"
                         : "=r"(bv.x), "=r"(bv.y), "=r"(bv.z), "=r"(bv.w)
                         : "r"(bfr + bt + (unsigned)(s * 512)));

            mma16816(acc,     a, bv.x, bv.y);   // n 0-7
            mma16816(acc + 4, a, bv.z, bv.w);   // n 8-15
        }
    }

    asm volatile("cp.async.wait_group 0;" ::: "memory");       // drain before smem reuse

    // ---- ssq reduce across the 4 lanes sharing each row ----
    float2 pa = unpk(ssqa), pb = unpk(ssqb);
    float sa = pa.x + pa.y, sb2 = pb.x + pb.y;
    sa  += __shfl_xor_sync(0xffffffffu, sa, 1);
    sa  += __shfl_xor_sync(0xffffffffu, sa, 2);
    sb2 += __shfl_xor_sync(0xffffffffu, sb2, 1);
    sb2 += __shfl_xor_sync(0xffffffffu, sb2, 2);

    // ---- stash D + ssq into this warp's (now free) x-stage smem ----
    float* dsm = (float*)(sm + warp * XWARP);   // 16 rows x 16 cols
    float* ssm = dsm + 256;
    {
        const int q = lane >> 2, i = lane & 3;
        dsm[q * 16 + 2 * i]            = acc[0];
        dsm[q * 16 + 2 * i + 1]        = acc[1];
        dsm[(q + 8) * 16 + 2 * i]      = acc[2];
        dsm[(q + 8) * 16 + 2 * i + 1]  = acc[3];
        dsm[q * 16 + 8 + 2 * i]        = acc[4];
        dsm[q * 16 + 9 + 2 * i]        = acc[5];
        dsm[(q + 8) * 16 + 8 + 2 * i]  = acc[6];
        dsm[(q + 8) * 16 + 9 + 2 * i]  = acc[7];
        if (i == 0) { ssm[q] = sa; ssm[q + 8] = sb2; }
    }
    __syncwarp();

    // ---- lanes 0-15: one row each -> scale, exp, Sinkhorn(20), store ----
    if (lane < 16) {
        const int row = lane;
        const float scale = rsqrtf(ssm[row] * (1.0f / (float)D) + 1.1920929e-07f);

        float m[16];
#pragma unroll
        for (int j = 0; j < 16; ++j)
            m[j] = __expf(fmaf(scale, dsm[row * 16 + j], bias[j]));

#pragma unroll 4
        for (int it = 0; it < 20; ++it) {
#pragma unroll
            for (int j = 0; j < 4; ++j) {              // column normalize
                float cs = m[j] + m[4 + j] + m[8 + j] + m[12 + j];
                float rc = __fdividef(1.0f, cs + 1e-8f);
                m[j] *= rc; m[4 + j] *= rc; m[8 + j] *= rc; m[12 + j] *= rc;
            }
#pragma unroll
            for (int i = 0; i < 4; ++i) {              // row normalize
                float rs = m[4 * i] + m[4 * i + 1] + m[4 * i + 2] + m[4 * i + 3];
                float rc = __fdividef(1.0f, rs + 1e-8f);
                m[4 * i] *= rc; m[4 * i + 1] *= rc; m[4 * i + 2] *= rc; m[4 * i + 3] *= rc;
            }
        }

        float4* o = (float4*)(out + (row0 + row) * NJ);
        o[0] = make_float4(m[0],  m[1],  m[2],  m[3]);
        o[1] = make_float4(m[4],  m[5],  m[6],  m[7]);
        o[2] = make_float4(m[8],  m[9],  m[10], m[11]);
        o[3] = make_float4(m[12], m[13], m[14], m[15]);
    }
}

extern "C" void kernel_launch(void* const* d_in, const int* in_sizes, int n_in,
                              void* d_out, int out_size)
{
    const float* x     = (const float*)d_in[0];
    const float* W     = (const float*)d_in[1];
    const float* bias  = (const float*)d_in[2];
    const float* alpha = (const float*)d_in[3];
    float* out = (float*)d_out;

    prep_kernel<<<128, 256>>>(W, alpha);

    cudaFuncSetAttribute(rsm_kernel, cudaFuncAttributeMaxDynamicSharedMemorySize, SMEM_B);

    rsm_kernel<<<NBLOCKS, THREADS, SMEM_B>>>(x, bias, out);
}